// round 2
// baseline (speedup 1.0000x reference)
#include <cuda_runtime.h>
#include <cuda_bf16.h>
#include <math.h>

// Problem constants
#define B_      2
#define LQ      4096
#define LKV     1024
#define D_      512
#define HEADS   8
#define DIMQK   64
#define DIMV    64
// SPAN=64, STRIDE=4 -> window: c-63 <= 4j <= c  (<=16 kv positions per query)

// Scratch (no cudaMalloc allowed)
__device__ float g_Q[B_ * LQ * D_];    // 16 MB
__device__ float g_K[B_ * LKV * D_];   // 4 MB
__device__ float g_V[B_ * LKV * D_];   // 4 MB
__device__ float g_ctx[B_ * LQ * D_];  // 16 MB

// ----------------------------------------------------------------------------
// SGEMM: C[M,N] = A[M,K] * B[K,N]; row-major; M%128==0, N%128==0, K%16==0
// 128x128 tile, BK=16, 256 threads, 8x8 per-thread microtile
// ----------------------------------------------------------------------------
__global__ __launch_bounds__(256, 2)
void sgemm128(const float* __restrict__ A, const float* __restrict__ Bm,
              float* __restrict__ C, int M, int N, int K) {
    const int BM = 128, BN = 128, BK = 16;
    __shared__ __align__(16) float As[BK][BM];
    __shared__ __align__(16) float Bs[BK][BN];

    const int block_row = blockIdx.y * BM;
    const int block_col = blockIdx.x * BN;
    const int tid = threadIdx.x;
    const int tr = tid / 16;   // 0..15
    const int tc = tid % 16;   // 0..15

    float acc[8][8];
#pragma unroll
    for (int i = 0; i < 8; i++)
#pragma unroll
        for (int j = 0; j < 8; j++) acc[i][j] = 0.f;

    // A-tile loads: 128x16 = 512 float4, 2 per thread
    const int a_row  = tid / 4;        // 0..63  (+64)
    const int a_col4 = tid % 4;        // float4 col index
    // B-tile loads: 16x128 = 512 float4, 2 per thread
    const int b_row  = tid / 32;       // 0..7   (+8)
    const int b_col4 = tid % 32;       // 0..31

    for (int k0 = 0; k0 < K; k0 += BK) {
#pragma unroll
        for (int i = 0; i < 2; i++) {
            int r = a_row + i * 64;
            float4 va = *(const float4*)&A[(size_t)(block_row + r) * K + k0 + a_col4 * 4];
            As[a_col4 * 4 + 0][r] = va.x;
            As[a_col4 * 4 + 1][r] = va.y;
            As[a_col4 * 4 + 2][r] = va.z;
            As[a_col4 * 4 + 3][r] = va.w;
        }
#pragma unroll
        for (int i = 0; i < 2; i++) {
            int r = b_row + i * 8;
            *(float4*)&Bs[r][b_col4 * 4] =
                *(const float4*)&Bm[(size_t)(k0 + r) * N + block_col + b_col4 * 4];
        }
        __syncthreads();

#pragma unroll
        for (int kk = 0; kk < BK; kk++) {
            float4 a0 = *(const float4*)&As[kk][tr * 8];
            float4 a1 = *(const float4*)&As[kk][tr * 8 + 4];
            float4 b0 = *(const float4*)&Bs[kk][tc * 8];
            float4 b1 = *(const float4*)&Bs[kk][tc * 8 + 4];
            float ar[8] = {a0.x, a0.y, a0.z, a0.w, a1.x, a1.y, a1.z, a1.w};
            float br[8] = {b0.x, b0.y, b0.z, b0.w, b1.x, b1.y, b1.z, b1.w};
#pragma unroll
            for (int i = 0; i < 8; i++)
#pragma unroll
                for (int j = 0; j < 8; j++)
                    acc[i][j] = fmaf(ar[i], br[j], acc[i][j]);
        }
        __syncthreads();
    }

#pragma unroll
    for (int i = 0; i < 8; i++) {
        int r = block_row + tr * 8 + i;
#pragma unroll
        for (int j = 0; j < 8; j += 4) {
            float4 v = make_float4(acc[i][j], acc[i][j + 1], acc[i][j + 2], acc[i][j + 3]);
            *(float4*)&C[(size_t)r * N + block_col + tc * 8 + j] = v;
        }
    }
}

// ----------------------------------------------------------------------------
// Sparse attention: one warp per (b, h, c).
// Q,K,V layout: [B, L, H*64] (head h at cols h*64 .. h*64+63)
// window: j in [max(0, ceil((c-63)/4)), floor(c/4)]
// ----------------------------------------------------------------------------
__global__ __launch_bounds__(256)
void sparse_attn_kernel(const float* __restrict__ Q, const float* __restrict__ K,
                        const float* __restrict__ V, float* __restrict__ ctx) {
    const int w = blockIdx.x * 8 + (threadIdx.x >> 5);
    const int lane = threadIdx.x & 31;

    const int c  = w % LQ;
    const int bh = w / LQ;
    const int h  = bh % HEADS;
    const int b  = bh / HEADS;

    const int j_lo = (c >= 63) ? ((c - 60) >> 2) : 0;  // ceil((c-63)/4), clamped at 0
    const int j_hi = c >> 2;                            // floor(c/4) <= 1023
    const int n = j_hi - j_lo + 1;                      // 1..16

    const int qoff = (b * LQ + c) * D_ + h * 64 + lane * 2;
    const float2 q2 = *(const float2*)&Q[qoff];

    float scores[16];
#pragma unroll
    for (int jj = 0; jj < 16; jj++) {
        float s = -1e30f;
        if (jj < n) {
            int j = j_lo + jj;
            const float2 k2 = *(const float2*)&K[(b * LKV + j) * D_ + h * 64 + lane * 2];
            float p = q2.x * k2.x + q2.y * k2.y;
            p += __shfl_xor_sync(0xFFFFFFFFu, p, 16);
            p += __shfl_xor_sync(0xFFFFFFFFu, p, 8);
            p += __shfl_xor_sync(0xFFFFFFFFu, p, 4);
            p += __shfl_xor_sync(0xFFFFFFFFu, p, 2);
            p += __shfl_xor_sync(0xFFFFFFFFu, p, 1);
            s = p * 0.125f;  // 1/sqrt(64)
        }
        scores[jj] = s;
    }

    float m = -1e30f;
#pragma unroll
    for (int jj = 0; jj < 16; jj++) m = fmaxf(m, scores[jj]);

    float wgt[16];
    float denom = 0.f;
#pragma unroll
    for (int jj = 0; jj < 16; jj++) {
        float e = (jj < n) ? __expf(scores[jj] - m) : 0.f;
        wgt[jj] = e;
        denom += e;
    }
    const float inv = 1.f / denom;

    float2 acc = make_float2(0.f, 0.f);
#pragma unroll
    for (int jj = 0; jj < 16; jj++) {
        if (jj < n) {
            int j = j_lo + jj;
            const float2 v2 = *(const float2*)&V[(b * LKV + j) * D_ + h * 64 + lane * 2];
            float wj = wgt[jj] * inv;
            acc.x = fmaf(wj, v2.x, acc.x);
            acc.y = fmaf(wj, v2.y, acc.y);
        }
    }
    *(float2*)&ctx[qoff] = acc;
}

// ----------------------------------------------------------------------------
extern "C" void kernel_launch(void* const* d_in, const int* in_sizes, int n_in,
                              void* d_out, int out_size) {
    const float* q    = (const float*)d_in[0];
    const float* k    = (const float*)d_in[1];
    const float* v    = (const float*)d_in[2];
    const float* Wq   = (const float*)d_in[3];
    const float* Wk   = (const float*)d_in[4];
    const float* Wv   = (const float*)d_in[5];
    const float* Wout = (const float*)d_in[6];
    float* out = (float*)d_out;

    float *Qp, *Kp, *Vp, *Ctx;
    cudaGetSymbolAddress((void**)&Qp,  g_Q);
    cudaGetSymbolAddress((void**)&Kp,  g_K);
    cudaGetSymbolAddress((void**)&Vp,  g_V);
    cudaGetSymbolAddress((void**)&Ctx, g_ctx);

    // Projections
    {
        dim3 gq(D_ / 128, (B_ * LQ) / 128);
        sgemm128<<<gq, 256>>>(q, Wq, Qp, B_ * LQ, D_, D_);
        dim3 gk(D_ / 128, (B_ * LKV) / 128);
        sgemm128<<<gk, 256>>>(k, Wk, Kp, B_ * LKV, D_, D_);
        sgemm128<<<gk, 256>>>(v, Wv, Vp, B_ * LKV, D_, D_);
    }

    // Sparse attention: B*H*Lq warps, 8 warps/block
    {
        int total_warps = B_ * HEADS * LQ;
        sparse_attn_kernel<<<total_warps / 8, 256>>>(Qp, Kp, Vp, Ctx);
    }

    // Output projection
    {
        dim3 go(D_ / 128, (B_ * LQ) / 128);
        sgemm128<<<go, 256>>>(Ctx, Wout, out, B_ * LQ, D_, D_);
    }
}

// round 8
// speedup vs baseline: 3.4720x; 3.4720x over previous
#include <cuda_runtime.h>
#include <cuda_bf16.h>
#include <math.h>
#include <stdint.h>

// Problem constants
#define B_      2
#define LQ      4096
#define LKV     1024
#define D_      512
#define HEADS   8
#define DIMQK   64
#define DIMV    64
// SPAN=64, STRIDE=4 -> window: c-63 <= 4j <= c  (<=16 kv positions per query)

// Scratch (no cudaMalloc allowed)
__device__ float g_Q[B_ * LQ * D_];    // 16 MB
__device__ float g_K[B_ * LKV * D_];   // 4 MB
__device__ float g_V[B_ * LKV * D_];   // 4 MB
__device__ float g_ctx[B_ * LQ * D_];  // 16 MB

// ----------------------------------------------------------------------------
// tf32 tensor-core GEMM: C[M,N] = A[M,K] * B[K,N], row-major.
// 128x128x32 block tile, 256 threads (8 warps, 2x4), warp tile 64x32,
// mma.sync.m16n8k8 tf32, cp.async double-buffered smem.
// Requires M%128==0, N%128==0, K%32==0.
// ----------------------------------------------------------------------------
#define AS_STRIDE 36   // 32 + 4 pad: fragment gather hits 32 distinct banks
#define BS_STRIDE 132  // 128 + 4 pad
#define SMEM_A_FLOATS (128 * AS_STRIDE)          // per stage
#define SMEM_B_FLOATS (32 * BS_STRIDE)           // per stage
#define GEMM_SMEM_BYTES ((2 * SMEM_A_FLOATS + 2 * SMEM_B_FLOATS) * 4)

__device__ __forceinline__ void cp_async16(uint32_t s, const void* g) {
    asm volatile("cp.async.cg.shared.global [%0], [%1], 16;\n" :: "r"(s), "l"(g));
}
__device__ __forceinline__ uint32_t f2tf(float x) {
    uint32_t r;
    asm("cvt.rna.tf32.f32 %0, %1;" : "=r"(r) : "f"(x));
    return r;
}

__global__ __launch_bounds__(256)
void gemm_tf32(const float* __restrict__ A, const float* __restrict__ B,
               float* __restrict__ C, int M, int N, int K) {
    extern __shared__ float smem[];
    float* sA = smem;                          // [2][128][AS_STRIDE]
    float* sB = smem + 2 * SMEM_A_FLOATS;      // [2][32][BS_STRIDE]

    const int tid  = threadIdx.x;
    const int wid  = tid >> 5;
    const int lane = tid & 31;
    const int gid  = lane >> 2;   // 0..7
    const int tig  = lane & 3;    // 0..3
    const int wm   = wid & 1;     // 0..1 (64 rows each)
    const int wn   = wid >> 1;    // 0..3 (32 cols each)
    const int brow = blockIdx.y * 128;
    const int bcol = blockIdx.x * 128;

    const uint32_t sA_u = (uint32_t)__cvta_generic_to_shared(sA);
    const uint32_t sB_u = (uint32_t)__cvta_generic_to_shared(sB);

    float acc[4][4][4] = {};

    const int T = K / 32;

    // prefetch tile 0 -> stage 0
    {
        const int k0 = 0, st = 0;
#pragma unroll
        for (int i = 0; i < 4; i++) {
            int f = tid + 256 * i;               // A: 1024 float4s
            int r = f >> 3, c4 = f & 7;
            cp_async16(sA_u + (uint32_t)(st * SMEM_A_FLOATS + r * AS_STRIDE + c4 * 4) * 4u,
                       &A[(size_t)(brow + r) * K + k0 + c4 * 4]);
        }
#pragma unroll
        for (int i = 0; i < 4; i++) {
            int f = tid + 256 * i;               // B: 1024 float4s
            int kk = f >> 5, n4 = f & 31;
            cp_async16(sB_u + (uint32_t)(st * SMEM_B_FLOATS + kk * BS_STRIDE + n4 * 4) * 4u,
                       &B[(size_t)(k0 + kk) * N + bcol + n4 * 4]);
        }
        asm volatile("cp.async.commit_group;\n");
    }

    for (int it = 0; it < T; it++) {
        asm volatile("cp.async.wait_group 0;\n");
        __syncthreads();

        if (it + 1 < T) {
            const int k0 = (it + 1) * 32, st = (it + 1) & 1;
#pragma unroll
            for (int i = 0; i < 4; i++) {
                int f = tid + 256 * i;
                int r = f >> 3, c4 = f & 7;
                cp_async16(sA_u + (uint32_t)(st * SMEM_A_FLOATS + r * AS_STRIDE + c4 * 4) * 4u,
                           &A[(size_t)(brow + r) * K + k0 + c4 * 4]);
            }
#pragma unroll
            for (int i = 0; i < 4; i++) {
                int f = tid + 256 * i;
                int kk = f >> 5, n4 = f & 31;
                cp_async16(sB_u + (uint32_t)(st * SMEM_B_FLOATS + kk * BS_STRIDE + n4 * 4) * 4u,
                           &B[(size_t)(k0 + kk) * N + bcol + n4 * 4]);
            }
            asm volatile("cp.async.commit_group;\n");
        }

        const float* cA = sA + (it & 1) * SMEM_A_FLOATS;
        const float* cB = sB + (it & 1) * SMEM_B_FLOATS;

#pragma unroll
        for (int ks = 0; ks < 4; ks++) {
            const int k = ks * 8;
            uint32_t a[4][4], b[4][2];
#pragma unroll
            for (int mi = 0; mi < 4; mi++) {
                int row = wm * 64 + mi * 16 + gid;
                a[mi][0] = f2tf(cA[row * AS_STRIDE + k + tig]);
                a[mi][1] = f2tf(cA[(row + 8) * AS_STRIDE + k + tig]);
                a[mi][2] = f2tf(cA[row * AS_STRIDE + k + tig + 4]);
                a[mi][3] = f2tf(cA[(row + 8) * AS_STRIDE + k + tig + 4]);
            }
#pragma unroll
            for (int ni = 0; ni < 4; ni++) {
                int col = wn * 32 + ni * 8 + gid;
                b[ni][0] = f2tf(cB[(k + tig) * BS_STRIDE + col]);
                b[ni][1] = f2tf(cB[(k + tig + 4) * BS_STRIDE + col]);
            }
#pragma unroll
            for (int mi = 0; mi < 4; mi++)
#pragma unroll
                for (int ni = 0; ni < 4; ni++) {
                    asm volatile(
                        "mma.sync.aligned.m16n8k8.row.col.f32.tf32.tf32.f32 "
                        "{%0,%1,%2,%3}, {%4,%5,%6,%7}, {%8,%9}, {%0,%1,%2,%3};\n"
                        : "+f"(acc[mi][ni][0]), "+f"(acc[mi][ni][1]),
                          "+f"(acc[mi][ni][2]), "+f"(acc[mi][ni][3])
                        : "r"(a[mi][0]), "r"(a[mi][1]), "r"(a[mi][2]), "r"(a[mi][3]),
                          "r"(b[ni][0]), "r"(b[ni][1]));
                }
        }
        __syncthreads();
    }

    // epilogue
#pragma unroll
    for (int mi = 0; mi < 4; mi++)
#pragma unroll
        for (int ni = 0; ni < 4; ni++) {
            int row = brow + wm * 64 + mi * 16 + gid;
            int col = bcol + wn * 32 + ni * 8 + tig * 2;
            float2 v0 = make_float2(acc[mi][ni][0], acc[mi][ni][1]);
            float2 v1 = make_float2(acc[mi][ni][2], acc[mi][ni][3]);
            *(float2*)&C[(size_t)row * N + col]       = v0;
            *(float2*)&C[(size_t)(row + 8) * N + col] = v1;
        }
}

// ----------------------------------------------------------------------------
// Sparse attention: one warp per (b, h, c).
// Q,K,V layout: [B, L, H*64] (head h at cols h*64 .. h*64+63)
// window: j in [max(0, ceil((c-63)/4)), floor(c/4)]
// ----------------------------------------------------------------------------
__global__ __launch_bounds__(256)
void sparse_attn_kernel(const float* __restrict__ Q, const float* __restrict__ K,
                        const float* __restrict__ V, float* __restrict__ ctx) {
    const int w = blockIdx.x * 8 + (threadIdx.x >> 5);
    const int lane = threadIdx.x & 31;

    const int c  = w % LQ;
    const int bh = w / LQ;
    const int h  = bh % HEADS;
    const int b  = bh / HEADS;

    const int j_lo = (c >= 63) ? ((c - 60) >> 2) : 0;  // ceil((c-63)/4), clamped at 0
    const int j_hi = c >> 2;                            // floor(c/4) <= 1023
    const int n = j_hi - j_lo + 1;                      // 1..16

    const int qoff = (b * LQ + c) * D_ + h * 64 + lane * 2;
    const float2 q2 = *(const float2*)&Q[qoff];

    float scores[16];
#pragma unroll
    for (int jj = 0; jj < 16; jj++) {
        float s = -1e30f;
        if (jj < n) {
            int j = j_lo + jj;
            const float2 k2 = *(const float2*)&K[(b * LKV + j) * D_ + h * 64 + lane * 2];
            float p = q2.x * k2.x + q2.y * k2.y;
            p += __shfl_xor_sync(0xFFFFFFFFu, p, 16);
            p += __shfl_xor_sync(0xFFFFFFFFu, p, 8);
            p += __shfl_xor_sync(0xFFFFFFFFu, p, 4);
            p += __shfl_xor_sync(0xFFFFFFFFu, p, 2);
            p += __shfl_xor_sync(0xFFFFFFFFu, p, 1);
            s = p * 0.125f;  // 1/sqrt(64)
        }
        scores[jj] = s;
    }

    float m = -1e30f;
#pragma unroll
    for (int jj = 0; jj < 16; jj++) m = fmaxf(m, scores[jj]);

    float wgt[16];
    float denom = 0.f;
#pragma unroll
    for (int jj = 0; jj < 16; jj++) {
        float e = (jj < n) ? __expf(scores[jj] - m) : 0.f;
        wgt[jj] = e;
        denom += e;
    }
    const float inv = 1.f / denom;

    float2 acc = make_float2(0.f, 0.f);
#pragma unroll
    for (int jj = 0; jj < 16; jj++) {
        if (jj < n) {
            int j = j_lo + jj;
            const float2 v2 = *(const float2*)&V[(b * LKV + j) * D_ + h * 64 + lane * 2];
            float wj = wgt[jj] * inv;
            acc.x = fmaf(wj, v2.x, acc.x);
            acc.y = fmaf(wj, v2.y, acc.y);
        }
    }
    *(float2*)&ctx[qoff] = acc;
}

// ----------------------------------------------------------------------------
extern "C" void kernel_launch(void* const* d_in, const int* in_sizes, int n_in,
                              void* d_out, int out_size) {
    const float* q    = (const float*)d_in[0];
    const float* k    = (const float*)d_in[1];
    const float* v    = (const float*)d_in[2];
    const float* Wq   = (const float*)d_in[3];
    const float* Wk   = (const float*)d_in[4];
    const float* Wv   = (const float*)d_in[5];
    const float* Wout = (const float*)d_in[6];
    float* out = (float*)d_out;

    float *Qp, *Kp, *Vp, *Ctx;
    cudaGetSymbolAddress((void**)&Qp,  g_Q);
    cudaGetSymbolAddress((void**)&Kp,  g_K);
    cudaGetSymbolAddress((void**)&Vp,  g_V);
    cudaGetSymbolAddress((void**)&Ctx, g_ctx);

    static int smem_set = 0;
    if (!smem_set) {
        cudaFuncSetAttribute(gemm_tf32, cudaFuncAttributeMaxDynamicSharedMemorySize,
                             GEMM_SMEM_BYTES);
        smem_set = 1;
    }

    // Projections (tf32 tensor cores)
    {
        dim3 gq(D_ / 128, (B_ * LQ) / 128);
        gemm_tf32<<<gq, 256, GEMM_SMEM_BYTES>>>(q, Wq, Qp, B_ * LQ, D_, D_);
        dim3 gk(D_ / 128, (B_ * LKV) / 128);
        gemm_tf32<<<gk, 256, GEMM_SMEM_BYTES>>>(k, Wk, Kp, B_ * LKV, D_, D_);
        gemm_tf32<<<gk, 256, GEMM_SMEM_BYTES>>>(v, Wv, Vp, B_ * LKV, D_, D_);
    }

    // Sparse attention: B*H*Lq warps, 8 warps/block
    {
        int total_warps = B_ * HEADS * LQ;
        sparse_attn_kernel<<<total_warps / 8, 256>>>(Qp, Kp, Vp, Ctx);
    }

    // Output projection (tf32 tensor cores)
    {
        dim3 go(D_ / 128, (B_ * LQ) / 128);
        gemm_tf32<<<go, 256, GEMM_SMEM_BYTES>>>(Ctx, Wout, out, B_ * LQ, D_, D_);
    }
}